// round 16
// baseline (speedup 1.0000x reference)
#include <cuda_runtime.h>
#include <math_constants.h>

#define NB 96
#define ND 128
#define NPAIR (NB * NB)
#define NCLS 8
#define NUND 4560                 // NB*(NB-1)/2 undirected pairs
#define BTHR 1024
#define MAXBLK 160
#define POSC 4608                 // >= worst-case undirected pos (4560) + padding
#define FULLM 0xffffffffu

// ---------------- device scratch (no allocations allowed) ----------------
__device__ float g_Dm[NPAIR];                   // diag never read (masked everywhere)
__device__ float g_bP[MAXBLK], g_bN[MAXBLK];    // per-block pos/neg distance partials
__device__ float g_pQ[MAXBLK], g_pT[MAXBLK];
__device__ unsigned g_pQC[MAXBLK], g_pTC[MAXBLK];
__device__ int g_done = 0;                      // kB completion counter; block 0 resets

// =====================================================================
// Kernel A: distance matrix + per-block masked-sum partials (no waits).
// =====================================================================
__global__ void __launch_bounds__(BTHR, 1)
kA(const float* __restrict__ E, const void* __restrict__ labp) {
    __shared__ int   sLab[NB];
    __shared__ unsigned sOK[2];
    __shared__ float sF1[32], sF2[32];

    const int t = threadIdx.x;
    const int wid = t >> 5, lid = t & 31;
    const int bid = blockIdx.x;
    const int nblk = gridDim.x;

    // chain A (E): decode pair, issue row loads — label-independent
    const int p = bid * 32 + wid;
    const bool have = p < NUND;
    int pi = 0, pj = 1;
    float4 va = make_float4(0.f, 0.f, 0.f, 0.f), vb = va;
    if (have) {
        float s = sqrtf((float)(36481 - 8 * p));
        int i = (int)((191.0f - s) * 0.5f);
        while ((i + 1) * (191 - (i + 1)) / 2 <= p) ++i;
        while (i * (191 - i) / 2 > p) --i;
        pi = i; pj = i + 1 + (p - i * (191 - i) / 2);
        va = ((const float4*)(E + pi * ND))[lid];      // DRAM, in flight
        vb = ((const float4*)(E + pj * ND))[lid];
    }
    // chain B (labels) round 1: int64 labels (values<8) have zero high words
    unsigned hiw = 0;
    if (t < 48) hiw = (unsigned)((const int*)labp)[2 * t + 1];
    if (wid < 2) {
        bool ok = (t < 48) ? (hiw == 0u) : true;
        unsigned m = __ballot_sync(FULLM, ok);
        if (lid == 0) sOK[wid] = m;
    }

    float dmv = 0.f;
    if (have) {
        float dx = va.x - vb.x, dy = va.y - vb.y, dz = va.z - vb.z, dw = va.w - vb.w;
        float d2 = dx * dx + dy * dy + dz * dz + dw * dw;
#pragma unroll
        for (int o = 16; o; o >>= 1) d2 += __shfl_down_sync(FULLM, d2, o);
        if (lid == 0) {
            dmv = sqrtf(fmaxf(d2, 0.f) + 1e-16f);
            g_Dm[pi * NB + pj] = dmv;
            g_Dm[pj * NB + pi] = dmv;
        }
    }

    __syncthreads();
    const bool is64 = (sOK[0] == FULLM) && (sOK[1] == FULLM);
    if (t < NB) sLab[t] = is64 ? (int)((const long long*)labp)[t]
                               : ((const int*)labp)[t];
    __syncthreads();

    float myPos = 0.f, myNeg = 0.f;
    if (have && lid == 0) {
        if (sLab[pi] == sLab[pj]) myPos = dmv; else myNeg = dmv;
    }
    // residual pairs (only if the grid is unexpectedly small)
    for (int p2 = p + nblk * 32; p2 < NUND; p2 += nblk * 32) {
        float s = sqrtf((float)(36481 - 8 * p2));
        int i = (int)((191.0f - s) * 0.5f);
        while ((i + 1) * (191 - (i + 1)) / 2 <= p2) ++i;
        while (i * (191 - i) / 2 > p2) --i;
        int j = i + 1 + (p2 - i * (191 - i) / 2);
        const float4 a2 = ((const float4*)(E + i * ND))[lid];
        const float4 b2 = ((const float4*)(E + j * ND))[lid];
        float dx = a2.x - b2.x, dy = a2.y - b2.y, dz = a2.z - b2.z, dw = a2.w - b2.w;
        float d2 = dx * dx + dy * dy + dz * dz + dw * dw;
#pragma unroll
        for (int o = 16; o; o >>= 1) d2 += __shfl_down_sync(FULLM, d2, o);
        if (lid == 0) {
            float dm = sqrtf(fmaxf(d2, 0.f) + 1e-16f);
            g_Dm[i * NB + j] = dm;
            g_Dm[j * NB + i] = dm;
            if (sLab[i] == sLab[j]) myPos += dm; else myNeg += dm;
        }
    }
    if (lid == 0) { sF1[wid] = myPos; sF2[wid] = myNeg; }
    __syncthreads();
    if (t == 0) {
        float pS = 0.f, nS = 0.f;
#pragma unroll
        for (int w = 0; w < 32; w++) { pS += sF1[w]; nS += sF2[w]; }
        g_bP[bid] = pS; g_bN[bid] = nS;      // kernel boundary orders these
    }
}

// =====================================================================
// Kernel B: build + quad + triplet + combine. Labels and g_Dm are L2-warm.
// =====================================================================
__global__ void __launch_bounds__(BTHR, 1)
kB(float* __restrict__ out, const void* __restrict__ labp, int nA) {
    __shared__ __align__(16) float sPD[POSC];   // 18 KB
    __shared__ int   sPM[POSC];                 // 18 KB
    __shared__ int   sLab[NB];
    __shared__ unsigned sOK[2];
    __shared__ int   sRowCnt[NB];
    __shared__ int   sRowStart[NB];
    __shared__ int   sOff[NCLS + 1];
    __shared__ int   sTot[NCLS];
    __shared__ float sF1[32], sF2[32];
    __shared__ unsigned sC1[32], sC2[32];
    __shared__ float sThr;

    const int t = threadIdx.x;
    const int wid = t >> 5, lid = t & 31;
    const int bid = blockIdx.x;
    const int nblk = gridDim.x;
    if (nA > MAXBLK) nA = MAXBLK;

    // label probe (L2-warm)
    unsigned hiw = 0;
    if (t < 48) hiw = (unsigned)((const int*)labp)[2 * t + 1];
    if (wid < 2) {
        bool ok = (t < 48) ? (hiw == 0u) : true;
        unsigned m = __ballot_sync(FULLM, ok);
        if (lid == 0) sOK[wid] = m;
    }
    __syncthreads();
    const bool is64 = (sOK[0] == FULLM) && (sOK[1] == FULLM);
    if (t < NB) sLab[t] = is64 ? (int)((const long long*)labp)[t]
                               : ((const int*)labp)[t];
    __syncthreads();

    // row-ballot pos counting: warp w owns rows w, w+32, w+64
#pragma unroll
    for (int rr = 0; rr < 3; rr++) {
        int r = wid + 32 * rr;
        int lr = sLab[r];
        int cnt = 0;
#pragma unroll
        for (int ch = 0; ch < 3; ch++) {
            int jj = ch * 32 + lid;
            unsigned m = __ballot_sync(FULLM, (jj > r) && (sLab[jj] == lr));
            cnt += __popc(m);
        }
        if (lid == 0) sRowCnt[r] = cnt;
    }
    __syncthreads();

    // warp 0: packed per-class scan + bases + thr
    if (wid == 0) {
        unsigned c0 = 0, c1 = 0, c2 = 0, c3 = 0;
#pragma unroll
        for (int ch = 0; ch < 3; ch++) {
            int r = ch * 32 + lid;
            int cnt = sRowCnt[r];
            int cr = sLab[r];
            unsigned f = (unsigned)cnt << ((cr & 1) * 16);
            unsigned p0 = ((cr >> 1) == 0) ? f : 0u;
            unsigned p1 = ((cr >> 1) == 1) ? f : 0u;
            unsigned p2 = ((cr >> 1) == 2) ? f : 0u;
            unsigned p3 = ((cr >> 1) == 3) ? f : 0u;
            unsigned i0 = p0, i1 = p1, i2 = p2, i3 = p3;
#pragma unroll
            for (int o = 1; o < 32; o <<= 1) {
                unsigned x0 = __shfl_up_sync(FULLM, i0, o);
                unsigned x1 = __shfl_up_sync(FULLM, i1, o);
                unsigned x2 = __shfl_up_sync(FULLM, i2, o);
                unsigned x3 = __shfl_up_sync(FULLM, i3, o);
                if (lid >= o) { i0 += x0; i1 += x1; i2 += x2; i3 += x3; }
            }
            unsigned e0 = i0 - p0 + c0, e1 = i1 - p1 + c1;
            unsigned e2 = i2 - p2 + c2, e3 = i3 - p3 + c3;
            unsigned sel = ((cr >> 1) == 0) ? e0 : ((cr >> 1) == 1) ? e1
                         : ((cr >> 1) == 2) ? e2 : e3;
            sRowCnt[r] = (int)((sel >> ((cr & 1) * 16)) & 0xFFFFu);
            c0 += __shfl_sync(FULLM, i0, 31);
            c1 += __shfl_sync(FULLM, i1, 31);
            c2 += __shfl_sync(FULLM, i2, 31);
            c3 += __shfl_sync(FULLM, i3, 31);
        }
        const int tt0 = (int)(c0 & 0xFFFFu), tt1 = (int)(c0 >> 16);
        const int tt2 = (int)(c1 & 0xFFFFu), tt3 = (int)(c1 >> 16);
        const int tt4 = (int)(c2 & 0xFFFFu), tt5 = (int)(c2 >> 16);
        const int tt6 = (int)(c3 & 0xFFFFu), tt7 = (int)(c3 >> 16);
        int bs0, bs1, bs2, bs3, bs4, bs5, bs6, bs7, b = 0;
        bs0 = b; b = (b + tt0 + 3) & ~3;  bs1 = b; b = (b + tt1 + 3) & ~3;
        bs2 = b; b = (b + tt2 + 3) & ~3;  bs3 = b; b = (b + tt3 + 3) & ~3;
        bs4 = b; b = (b + tt4 + 3) & ~3;  bs5 = b; b = (b + tt5 + 3) & ~3;
        bs6 = b; b = (b + tt6 + 3) & ~3;  bs7 = b; b = (b + tt7 + 3) & ~3;
        if (lid == 0) {
            sOff[0] = bs0; sOff[1] = bs1; sOff[2] = bs2; sOff[3] = bs3;
            sOff[4] = bs4; sOff[5] = bs5; sOff[6] = bs6; sOff[7] = bs7;
            sOff[8] = b;
            sTot[0] = tt0; sTot[1] = tt1; sTot[2] = tt2; sTot[3] = tt3;
            sTot[4] = tt4; sTot[5] = tt5; sTot[6] = tt6; sTot[7] = tt7;
        }
#pragma unroll
        for (int ch = 0; ch < 3; ch++) {
            int r = ch * 32 + lid;
            int cr = sLab[r];
            int bc = bs0;
            bc = (cr == 1) ? bs1 : bc;  bc = (cr == 2) ? bs2 : bc;
            bc = (cr == 3) ? bs3 : bc;  bc = (cr == 4) ? bs4 : bc;
            bc = (cr == 5) ? bs5 : bc;  bc = (cr == 6) ? bs6 : bc;
            bc = (cr == 7) ? bs7 : bc;
            sRowStart[r] = bc + sRowCnt[r];
        }
        // thr from kernel-A partials (L2-warm; deterministic order)
        float pS = 0.f, nS = 0.f;
        for (int x = lid; x < nA; x += 32) { pS += g_bP[x]; nS += g_bN[x]; }
#pragma unroll
        for (int o = 16; o; o >>= 1) {
            pS += __shfl_down_sync(FULLM, pS, o);
            nS += __shfl_down_sync(FULLM, nS, o);
        }
        if (lid == 0) {
            int nposU = tt0 + tt1 + tt2 + tt3 + tt4 + tt5 + tt6 + tt7;
            float cpos = 2.f * (float)nposU;
            float cneg = (float)(NPAIR - NB) - cpos;
            float mu = (cpos > 0.f && cneg > 0.f)
                       ? ((2.f * nS) / cneg - (2.f * pS) / cpos) : 0.f;
            sThr = fmaxf(mu, 0.f);
        }
    }
    __syncthreads();
    const int base8 = sOff[NCLS];

    // pad init: exactly the <=3 alignment slots per class (disjoint from scatter)
    if (t >= 32 && t < 56) {
        int idx = t - 32, c = idx / 3, k = idx - c * 3;
        int slot = sOff[c] + sTot[c] + k;
        if (slot < sOff[c + 1]) { sPD[slot] = -CUDART_INF_F; sPM[slot] = 0; }
    }

    // ballot scatter (g_Dm is L2-warm); writes only real slots
#pragma unroll
    for (int rr = 0; rr < 3; rr++) {
        int r = wid + 32 * rr;
        int lr = sLab[r];
        int run = sRowStart[r];
#pragma unroll
        for (int ch = 0; ch < 3; ch++) {
            int jj = ch * 32 + lid;
            bool pred = (jj > r) && (sLab[jj] == lr);
            unsigned m = __ballot_sync(FULLM, pred);
            if (pred) {
                int slot = run + __popc(m & ((1u << lid) - 1u));
                sPD[slot] = g_Dm[r * NB + jj];
                sPM[slot] = r | (jj << 8) | (lr << 16);
            }
            run += __popc(m);
        }
    }
    __syncthreads();

    const float thr = sThr, thrh = 0.5f * thr;

    // quad (undirected neg, weighted) + triplet
    float qs0 = 0.f, qs1 = 0.f, qs2 = 0.f, qs3 = 0.f, ts = 0.f;
    unsigned qc0 = 0, qc1 = 0, qc2 = 0, qc3 = 0, tc = 0;
    const int gt = bid * BTHR + t;
    const int GT = nblk * BTHR;

    const int qTot = NPAIR * NCLS * 4;
    for (int e = gt; e < qTot; e += GT) {
        int idx = e >> 5;
        int ii = idx / NB, jj = idx - ii * NB;
        if (ii >= jj) continue;
        int li = sLab[ii], lj = sLab[jj];
        if (li == lj) continue;
        float b = g_Dm[idx];
        int seg = (e >> 2) & 7, quar = e & 3;
        int lo = sOff[seg], hi = sOff[seg + 1];
        int qlen = ((hi - lo + 15) >> 4) << 2;
        int xs = lo + quar * qlen;
        int xe = min(xs + qlen, hi);
        float wi = (float)(2 - (seg == li) - (seg == lj));   // in {1,2}
        for (int x = xs; x < xe; x += 4) {
            const float4 v = *reinterpret_cast<const float4*>(&sPD[x]);
            float d0 = b - v.x, d1 = b - v.y, d2 = b - v.z, d3 = b - v.w;
            unsigned wiu = (unsigned)wi;
            if (d0 < thrh) { qc0 += wiu; qs0 = fmaf(wi, fmaxf(d0, 0.f), qs0); }
            if (d1 < thrh) { qc1 += wiu; qs1 = fmaf(wi, fmaxf(d1, 0.f), qs1); }
            if (d2 < thrh) { qc2 += wiu; qs2 = fmaf(wi, fmaxf(d2, 0.f), qs2); }
            if (d3 < thrh) { qc3 += wiu; qs3 = fmaf(wi, fmaxf(d3, 0.f), qs3); }
        }
    }
    float qs = (qs0 + qs1) + (qs2 + qs3);
    unsigned qc = (qc0 + qc1) + (qc2 + qc3);

    for (int e = gt; e < base8 * NB; e += GT) {
        int pp = e / NB, k = e - pp * NB;
        int meta = sPM[pp];
        int ai = meta & 255, aj = (meta >> 8) & 255, c = meta >> 16;
        float dij = sPD[pp];                       // -INF pads => skipped
        if (sLab[k] != c) {
            float tv1 = g_Dm[ai * NB + k] - dij;
            float tv2 = g_Dm[aj * NB + k] - dij;
            if (tv1 < thr) { tc++; ts += fmaxf(tv1, 0.f); }
            if (tv2 < thr) { tc++; ts += fmaxf(tv2, 0.f); }
        }
    }

    // block reduce, publish, combine
#pragma unroll
    for (int o = 16; o; o >>= 1) {
        qs += __shfl_down_sync(FULLM, qs, o);
        ts += __shfl_down_sync(FULLM, ts, o);
        qc += __shfl_down_sync(FULLM, qc, o);
        tc += __shfl_down_sync(FULLM, tc, o);
    }
    if ((t & 31) == 0) { sF1[wid] = qs; sF2[wid] = ts; sC1[wid] = qc; sC2[wid] = tc; }
    __syncthreads();
    if (t == 0) {
        float a = 0.f, b2 = 0.f; unsigned u1 = 0, u2 = 0;
#pragma unroll
        for (int w = 0; w < 32; w++) { a += sF1[w]; b2 += sF2[w]; u1 += sC1[w]; u2 += sC2[w]; }
        g_pQ[bid] = a; g_pT[bid] = b2; g_pQC[bid] = u1; g_pTC[bid] = u2;
        __threadfence();
        atomicAdd(&g_done, 1);                     // fire-and-forget completion
    }
    if (bid != 0) return;

    // block 0, warp 0: single-address poll, combine, write, reset
    if (wid == 0) {
        if (lid == 0) {
            while (*(volatile int*)&g_done < nblk) { }
        }
        __syncwarp();
        __threadfence();
        float a = 0.f, b2 = 0.f; unsigned u1 = 0, u2 = 0;
        for (int x = lid; x < nblk; x += 32) {
            a += g_pQ[x]; b2 += g_pT[x]; u1 += g_pQC[x]; u2 += g_pTC[x];
        }
#pragma unroll
        for (int o = 16; o; o >>= 1) {
            a  += __shfl_down_sync(FULLM, a, o);
            b2 += __shfl_down_sync(FULLM, b2, o);
            u1 += __shfl_down_sync(FULLM, u1, o);
            u2 += __shfl_down_sync(FULLM, u2, o);
        }
        if (lid == 0) {
            float tl = (u2 > 0) ? b2 / (float)u2 : 0.f;
            float ql = (u1 > 0) ? a / (float)u1 : 0.f;
            out[0] = tl + ql;
            g_done = 0;                            // reset for next replay
        }
    }
}

extern "C" void kernel_launch(void* const* d_in, const int* in_sizes, int n_in,
                              void* d_out, int out_size) {
    const float* E = (const float*)d_in[0];
    const void* lab = d_in[1];
    (void)in_sizes; (void)n_in; (void)out_size;
    int sms = 148;
    cudaDeviceGetAttribute(&sms, cudaDevAttrMultiProcessorCount, 0);
    int grid = sms < MAXBLK ? sms : MAXBLK;
    // kB's completion poll requires single-wave residency
    int perSM = 1;
    cudaOccupancyMaxActiveBlocksPerMultiprocessor(&perSM, kB, BTHR, 0);
    if (perSM < 1) perSM = 1;
    long cap = (long)perSM * sms;
    if (grid > cap) grid = (int)cap;
    if (grid < 1) grid = 1;
    kA<<<grid, BTHR>>>(E, lab);
    kB<<<grid, BTHR>>>((float*)d_out, lab, grid);
}

// round 17
// speedup vs baseline: 1.0121x; 1.0121x over previous
#include <cuda_runtime.h>
#include <math_constants.h>

#define NB 96
#define ND 128
#define NPAIR (NB * NB)
#define NCLS 8
#define NUND 4560                 // NB*(NB-1)/2 undirected pairs
#define BTHR 1024
#define MAXBLK 160
#define POSC 4608                 // >= worst-case undirected pos (4560) + padding
#define FULLM 0xffffffffu

// ---------------- device scratch (no allocations allowed) ----------------
__device__ float g_Dm[NPAIR];                   // diag never read (masked everywhere)
__device__ __align__(16) float g_PD[POSC];      // class-grouped pos distances
__device__ __align__(16) int   g_PM[POSC];      // pos metadata i|(j<<8)|(cls<<16)
__device__ int   g_off[10];                     // [0..8] segment offsets, [9] nposU
__device__ float g_bP[MAXBLK], g_bN[MAXBLK];    // per-block pos/neg distance partials
__device__ float g_pQ[MAXBLK], g_pT[MAXBLK];
__device__ unsigned g_pQC[MAXBLK], g_pTC[MAXBLK];
__device__ int g_done = 0;                      // kB completion counter; block 0 resets

// =====================================================================
// Kernel A: distances + pos-list build (overlapped with DRAM stalls)
// + per-block masked-sum partials. No waits.
// =====================================================================
__global__ void __launch_bounds__(BTHR, 1)
kA(const float* __restrict__ E, const void* __restrict__ labp) {
    __shared__ int   sLab[NB];
    __shared__ unsigned sOK[2];
    __shared__ int   sRowCnt[NB];               // counts, then per-class row prefix
    __shared__ int   sRowStart[NB];
    __shared__ int   sOff[NCLS + 1];
    __shared__ int   sTot[NCLS];
    __shared__ int   sNposU;
    __shared__ float sF1[32], sF2[32];

    const int t = threadIdx.x;
    const int wid = t >> 5, lid = t & 31;
    const int bid = blockIdx.x;
    const int nblk = gridDim.x;

    // chain A (E): decode pair, issue row loads — label-independent
    const int p = bid * 32 + wid;
    const bool have = p < NUND;
    int pi = 0, pj = 1;
    float4 va = make_float4(0.f, 0.f, 0.f, 0.f), vb = va;
    if (have) {
        float s = sqrtf((float)(36481 - 8 * p));
        int i = (int)((191.0f - s) * 0.5f);
        while ((i + 1) * (191 - (i + 1)) / 2 <= p) ++i;
        while (i * (191 - i) / 2 > p) --i;
        pi = i; pj = i + 1 + (p - i * (191 - i) / 2);
        va = ((const float4*)(E + pi * ND))[lid];      // DRAM, in flight
        vb = ((const float4*)(E + pj * ND))[lid];
    }
    // chain B (labels) round 1: int64 labels (values<8) have zero high words
    unsigned hiw = 0;
    if (t < 48) hiw = (unsigned)((const int*)labp)[2 * t + 1];
    if (wid < 2) {
        bool ok = (t < 48) ? (hiw == 0u) : true;
        unsigned m = __ballot_sync(FULLM, ok);
        if (lid == 0) sOK[wid] = m;
    }

    float dmv = 0.f;
    if (have) {
        float dx = va.x - vb.x, dy = va.y - vb.y, dz = va.z - vb.z, dw = va.w - vb.w;
        float d2 = dx * dx + dy * dy + dz * dz + dw * dw;
#pragma unroll
        for (int o = 16; o; o >>= 1) d2 += __shfl_down_sync(FULLM, d2, o);
        if (lid == 0) {
            dmv = sqrtf(fmaxf(d2, 0.f) + 1e-16f);
            g_Dm[pi * NB + pj] = dmv;
            g_Dm[pj * NB + pi] = dmv;
        }
    }

    __syncthreads();
    const bool is64 = (sOK[0] == FULLM) && (sOK[1] == FULLM);
    if (t < NB) sLab[t] = is64 ? (int)((const long long*)labp)[t]
                               : ((const int*)labp)[t];
    __syncthreads();

    // row-ballot pos counting: warp w owns rows w, w+32, w+64
#pragma unroll
    for (int rr = 0; rr < 3; rr++) {
        int r = wid + 32 * rr;
        int lr = sLab[r];
        int cnt = 0;
#pragma unroll
        for (int ch = 0; ch < 3; ch++) {
            int jj = ch * 32 + lid;
            unsigned m = __ballot_sync(FULLM, (jj > r) && (sLab[jj] == lr));
            cnt += __popc(m);
        }
        if (lid == 0) sRowCnt[r] = cnt;
    }
    __syncthreads();

    // warp 0: packed per-class exclusive scan over 96 row counts -> offsets
    if (wid == 0) {
        unsigned c0 = 0, c1 = 0, c2 = 0, c3 = 0;
#pragma unroll
        for (int ch = 0; ch < 3; ch++) {
            int r = ch * 32 + lid;
            int cnt = sRowCnt[r];
            int cr = sLab[r];
            unsigned f = (unsigned)cnt << ((cr & 1) * 16);
            unsigned p0 = ((cr >> 1) == 0) ? f : 0u;
            unsigned p1 = ((cr >> 1) == 1) ? f : 0u;
            unsigned p2 = ((cr >> 1) == 2) ? f : 0u;
            unsigned p3 = ((cr >> 1) == 3) ? f : 0u;
            unsigned i0 = p0, i1 = p1, i2 = p2, i3 = p3;
#pragma unroll
            for (int o = 1; o < 32; o <<= 1) {
                unsigned x0 = __shfl_up_sync(FULLM, i0, o);
                unsigned x1 = __shfl_up_sync(FULLM, i1, o);
                unsigned x2 = __shfl_up_sync(FULLM, i2, o);
                unsigned x3 = __shfl_up_sync(FULLM, i3, o);
                if (lid >= o) { i0 += x0; i1 += x1; i2 += x2; i3 += x3; }
            }
            unsigned e0 = i0 - p0 + c0, e1 = i1 - p1 + c1;
            unsigned e2 = i2 - p2 + c2, e3 = i3 - p3 + c3;
            unsigned sel = ((cr >> 1) == 0) ? e0 : ((cr >> 1) == 1) ? e1
                         : ((cr >> 1) == 2) ? e2 : e3;
            sRowCnt[r] = (int)((sel >> ((cr & 1) * 16)) & 0xFFFFu);
            c0 += __shfl_sync(FULLM, i0, 31);
            c1 += __shfl_sync(FULLM, i1, 31);
            c2 += __shfl_sync(FULLM, i2, 31);
            c3 += __shfl_sync(FULLM, i3, 31);
        }
        const int tt0 = (int)(c0 & 0xFFFFu), tt1 = (int)(c0 >> 16);
        const int tt2 = (int)(c1 & 0xFFFFu), tt3 = (int)(c1 >> 16);
        const int tt4 = (int)(c2 & 0xFFFFu), tt5 = (int)(c2 >> 16);
        const int tt6 = (int)(c3 & 0xFFFFu), tt7 = (int)(c3 >> 16);
        int bs0, bs1, bs2, bs3, bs4, bs5, bs6, bs7, b = 0;
        bs0 = b; b = (b + tt0 + 3) & ~3;  bs1 = b; b = (b + tt1 + 3) & ~3;
        bs2 = b; b = (b + tt2 + 3) & ~3;  bs3 = b; b = (b + tt3 + 3) & ~3;
        bs4 = b; b = (b + tt4 + 3) & ~3;  bs5 = b; b = (b + tt5 + 3) & ~3;
        bs6 = b; b = (b + tt6 + 3) & ~3;  bs7 = b; b = (b + tt7 + 3) & ~3;
        if (lid == 0) {
            sOff[0] = bs0; sOff[1] = bs1; sOff[2] = bs2; sOff[3] = bs3;
            sOff[4] = bs4; sOff[5] = bs5; sOff[6] = bs6; sOff[7] = bs7;
            sOff[8] = b;
            sTot[0] = tt0; sTot[1] = tt1; sTot[2] = tt2; sTot[3] = tt3;
            sTot[4] = tt4; sTot[5] = tt5; sTot[6] = tt6; sTot[7] = tt7;
            sNposU = tt0 + tt1 + tt2 + tt3 + tt4 + tt5 + tt6 + tt7;
        }
#pragma unroll
        for (int ch = 0; ch < 3; ch++) {
            int r = ch * 32 + lid;
            int cr = sLab[r];
            int bc = bs0;
            bc = (cr == 1) ? bs1 : bc;  bc = (cr == 2) ? bs2 : bc;
            bc = (cr == 3) ? bs3 : bc;  bc = (cr == 4) ? bs4 : bc;
            bc = (cr == 5) ? bs5 : bc;  bc = (cr == 6) ? bs6 : bc;
            bc = (cr == 7) ? bs7 : bc;
            sRowStart[r] = bc + sRowCnt[r];
        }
    }
    __syncthreads();

    // block 0 publishes offsets, nposU, and the <=3 pad slots per class
    if (bid == 0) {
        if (t < 9) g_off[t] = sOff[t];
        if (t == 9) g_off[9] = sNposU;
        if (t >= 32 && t < 56) {
            int idx = t - 32, c = idx / 3, k = idx - c * 3;
            int slot = sOff[c] + sTot[c] + k;
            if (slot < sOff[c + 1]) { g_PD[slot] = -CUDART_INF_F; g_PM[slot] = 0; }
        }
    }

    // each warp writes its pos pair directly into the global class-grouped list;
    // slot = rowStart[pi] + rank of pj within row pi (3 ballots, deterministic)
    float myPos = 0.f, myNeg = 0.f;
    if (have) {
        int li = sLab[pi];
        bool isPos = (li == sLab[pj]);             // warp-uniform
        if (isPos) {
            int rank = 0;
#pragma unroll
            for (int ch = 0; ch < 3; ch++) {
                int q = ch * 32 + lid;
                unsigned m = __ballot_sync(FULLM, (q > pi) && (q < pj) && (sLab[q] == li));
                rank += __popc(m);
            }
            if (lid == 0) {
                int slot = sRowStart[pi] + rank;
                g_PD[slot] = dmv;
                g_PM[slot] = pi | (pj << 8) | (li << 16);
                myPos = dmv;
            }
        } else if (lid == 0) {
            myNeg = dmv;
        }
    }
    // residual pairs (only if the grid is unexpectedly small)
    for (int p2 = p + nblk * 32; p2 < NUND; p2 += nblk * 32) {
        float s = sqrtf((float)(36481 - 8 * p2));
        int i = (int)((191.0f - s) * 0.5f);
        while ((i + 1) * (191 - (i + 1)) / 2 <= p2) ++i;
        while (i * (191 - i) / 2 > p2) --i;
        int j = i + 1 + (p2 - i * (191 - i) / 2);
        const float4 a2 = ((const float4*)(E + i * ND))[lid];
        const float4 b2 = ((const float4*)(E + j * ND))[lid];
        float dx = a2.x - b2.x, dy = a2.y - b2.y, dz = a2.z - b2.z, dw = a2.w - b2.w;
        float d2 = dx * dx + dy * dy + dz * dz + dw * dw;
#pragma unroll
        for (int o = 16; o; o >>= 1) d2 += __shfl_down_sync(FULLM, d2, o);
        float dm = __shfl_sync(FULLM, sqrtf(fmaxf(d2, 0.f) + 1e-16f), 0);
        int li = sLab[i];
        if (li == sLab[j]) {
            int rank = 0;
#pragma unroll
            for (int ch = 0; ch < 3; ch++) {
                int q = ch * 32 + lid;
                unsigned m = __ballot_sync(FULLM, (q > i) && (q < j) && (sLab[q] == li));
                rank += __popc(m);
            }
            if (lid == 0) {
                g_Dm[i * NB + j] = dm; g_Dm[j * NB + i] = dm;
                g_PD[sRowStart[i] + rank] = dm;
                g_PM[sRowStart[i] + rank] = i | (j << 8) | (li << 16);
                myPos += dm;
            }
        } else if (lid == 0) {
            g_Dm[i * NB + j] = dm; g_Dm[j * NB + i] = dm;
            myNeg += dm;
        }
    }
    if (lid == 0) { sF1[wid] = myPos; sF2[wid] = myNeg; }
    __syncthreads();
    if (t == 0) {
        float pS = 0.f, nS = 0.f;
#pragma unroll
        for (int w = 0; w < 32; w++) { pS += sF1[w]; nS += sF2[w]; }
        g_bP[bid] = pS; g_bN[bid] = nS;      // kernel boundary orders all of this
    }
}

// =====================================================================
// Kernel B: bulk-copy prebuilt pos list, thr, quad + triplet + combine.
// Everything it reads is L2-warm from kA.
// =====================================================================
__global__ void __launch_bounds__(BTHR, 1)
kB(float* __restrict__ out, const void* __restrict__ labp, int nA) {
    __shared__ __align__(16) float sPD[POSC];   // 18 KB
    __shared__ __align__(16) int   sPM[POSC];   // 18 KB
    __shared__ int   sLab[NB];
    __shared__ unsigned sOK[2];
    __shared__ int   sOff[10];
    __shared__ float sF1[32], sF2[32];
    __shared__ unsigned sC1[32], sC2[32];
    __shared__ float sThr;

    const int t = threadIdx.x;
    const int wid = t >> 5, lid = t & 31;
    const int bid = blockIdx.x;
    const int nblk = gridDim.x;
    if (nA > MAXBLK) nA = MAXBLK;

    // issue offset load + label probe concurrently (both L2-warm)
    if (t < 10) sOff[t] = g_off[t];
    unsigned hiw = 0;
    if (t < 48) hiw = (unsigned)((const int*)labp)[2 * t + 1];
    if (wid < 2) {
        bool ok = (t < 48) ? (hiw == 0u) : true;
        unsigned m = __ballot_sync(FULLM, ok);
        if (lid == 0) sOK[wid] = m;
    }
    __syncthreads();
    const int base8 = sOff[8];

    // bulk copy of the prebuilt pos list (base8 is a multiple of 4)
    {
        const float4* gp4 = reinterpret_cast<const float4*>(g_PD);
        const int4*   gm4 = reinterpret_cast<const int4*>(g_PM);
        float4* sp4 = reinterpret_cast<float4*>(sPD);
        int4*   sm4 = reinterpret_cast<int4*>(sPM);
        for (int x = t; x < (base8 >> 2); x += BTHR) { sp4[x] = gp4[x]; sm4[x] = gm4[x]; }
    }
    const bool is64 = (sOK[0] == FULLM) && (sOK[1] == FULLM);
    if (t < NB) sLab[t] = is64 ? (int)((const long long*)labp)[t]
                               : ((const int*)labp)[t];

    // warp 0: thr from kA partials (deterministic fixed order)
    if (wid == 0) {
        float pS = 0.f, nS = 0.f;
        for (int x = lid; x < nA; x += 32) { pS += g_bP[x]; nS += g_bN[x]; }
#pragma unroll
        for (int o = 16; o; o >>= 1) {
            pS += __shfl_down_sync(FULLM, pS, o);
            nS += __shfl_down_sync(FULLM, nS, o);
        }
        if (lid == 0) {
            float cpos = 2.f * (float)sOff[9];               // directed same-label pairs
            float cneg = (float)(NPAIR - NB) - cpos;
            float mu = (cpos > 0.f && cneg > 0.f)
                       ? ((2.f * nS) / cneg - (2.f * pS) / cpos) : 0.f;
            sThr = fmaxf(mu, 0.f);
        }
    }
    __syncthreads();

    const float thr = sThr, thrh = 0.5f * thr;

    // quad (undirected neg, weighted) + triplet
    float qs0 = 0.f, qs1 = 0.f, qs2 = 0.f, qs3 = 0.f, ts = 0.f;
    unsigned qc0 = 0, qc1 = 0, qc2 = 0, qc3 = 0, tc = 0;
    const int gt = bid * BTHR + t;
    const int GT = nblk * BTHR;

    const int qTot = NPAIR * NCLS * 4;
    for (int e = gt; e < qTot; e += GT) {
        int idx = e >> 5;
        int ii = idx / NB, jj = idx - ii * NB;
        if (ii >= jj) continue;
        int li = sLab[ii], lj = sLab[jj];
        if (li == lj) continue;
        float b = g_Dm[idx];
        int seg = (e >> 2) & 7, quar = e & 3;
        int lo = sOff[seg], hi = sOff[seg + 1];
        int qlen = ((hi - lo + 15) >> 4) << 2;
        int xs = lo + quar * qlen;
        int xe = min(xs + qlen, hi);
        float wi = (float)(2 - (seg == li) - (seg == lj));   // in {1,2}
        unsigned wiu = (unsigned)wi;
        for (int x = xs; x < xe; x += 4) {
            const float4 v = *reinterpret_cast<const float4*>(&sPD[x]);
            float d0 = b - v.x, d1 = b - v.y, d2 = b - v.z, d3 = b - v.w;
            if (d0 < thrh) { qc0 += wiu; qs0 = fmaf(wi, fmaxf(d0, 0.f), qs0); }
            if (d1 < thrh) { qc1 += wiu; qs1 = fmaf(wi, fmaxf(d1, 0.f), qs1); }
            if (d2 < thrh) { qc2 += wiu; qs2 = fmaf(wi, fmaxf(d2, 0.f), qs2); }
            if (d3 < thrh) { qc3 += wiu; qs3 = fmaf(wi, fmaxf(d3, 0.f), qs3); }
        }
    }
    float qs = (qs0 + qs1) + (qs2 + qs3);
    unsigned qc = (qc0 + qc1) + (qc2 + qc3);

    for (int e = gt; e < base8 * NB; e += GT) {
        int pp = e / NB, k = e - pp * NB;
        int meta = sPM[pp];
        int ai = meta & 255, aj = (meta >> 8) & 255, c = meta >> 16;
        float dij = sPD[pp];                       // -INF pads => skipped
        if (sLab[k] != c) {
            float tv1 = g_Dm[ai * NB + k] - dij;
            float tv2 = g_Dm[aj * NB + k] - dij;
            if (tv1 < thr) { tc++; ts += fmaxf(tv1, 0.f); }
            if (tv2 < thr) { tc++; ts += fmaxf(tv2, 0.f); }
        }
    }

    // block reduce, publish, combine
#pragma unroll
    for (int o = 16; o; o >>= 1) {
        qs += __shfl_down_sync(FULLM, qs, o);
        ts += __shfl_down_sync(FULLM, ts, o);
        qc += __shfl_down_sync(FULLM, qc, o);
        tc += __shfl_down_sync(FULLM, tc, o);
    }
    if ((t & 31) == 0) { sF1[wid] = qs; sF2[wid] = ts; sC1[wid] = qc; sC2[wid] = tc; }
    __syncthreads();
    if (t == 0) {
        float a = 0.f, b2 = 0.f; unsigned u1 = 0, u2 = 0;
#pragma unroll
        for (int w = 0; w < 32; w++) { a += sF1[w]; b2 += sF2[w]; u1 += sC1[w]; u2 += sC2[w]; }
        g_pQ[bid] = a; g_pT[bid] = b2; g_pQC[bid] = u1; g_pTC[bid] = u2;
        __threadfence();
        atomicAdd(&g_done, 1);                     // fire-and-forget completion
    }
    if (bid != 0) return;

    // block 0, warp 0: single-address poll, combine, write, reset
    if (wid == 0) {
        if (lid == 0) {
            while (*(volatile int*)&g_done < nblk) { }
        }
        __syncwarp();
        __threadfence();
        float a = 0.f, b2 = 0.f; unsigned u1 = 0, u2 = 0;
        for (int x = lid; x < nblk; x += 32) {
            a += g_pQ[x]; b2 += g_pT[x]; u1 += g_pQC[x]; u2 += g_pTC[x];
        }
#pragma unroll
        for (int o = 16; o; o >>= 1) {
            a  += __shfl_down_sync(FULLM, a, o);
            b2 += __shfl_down_sync(FULLM, b2, o);
            u1 += __shfl_down_sync(FULLM, u1, o);
            u2 += __shfl_down_sync(FULLM, u2, o);
        }
        if (lid == 0) {
            float tl = (u2 > 0) ? b2 / (float)u2 : 0.f;
            float ql = (u1 > 0) ? a / (float)u1 : 0.f;
            out[0] = tl + ql;
            g_done = 0;                            // reset for next replay
        }
    }
}

extern "C" void kernel_launch(void* const* d_in, const int* in_sizes, int n_in,
                              void* d_out, int out_size) {
    const float* E = (const float*)d_in[0];
    const void* lab = d_in[1];
    (void)in_sizes; (void)n_in; (void)out_size;
    int sms = 148;
    cudaDeviceGetAttribute(&sms, cudaDevAttrMultiProcessorCount, 0);
    int grid = sms < MAXBLK ? sms : MAXBLK;
    // kB's completion poll requires single-wave residency
    int perSM = 1;
    cudaOccupancyMaxActiveBlocksPerMultiprocessor(&perSM, kB, BTHR, 0);
    if (perSM < 1) perSM = 1;
    long cap = (long)perSM * sms;
    if (grid > cap) grid = (int)cap;
    if (grid < 1) grid = 1;
    kA<<<grid, BTHR>>>(E, lab);
    kB<<<grid, BTHR>>>((float*)d_out, lab, grid);
}